// round 1
// baseline (speedup 1.0000x reference)
#include <cuda_runtime.h>
#include <cuda_bf16.h>
#include <math.h>

// Problem constants
#define T_TOK   16384      // 4*4096 tokens
#define HDIM    4096
#define NEXP    64
#define TOPK    8
#define ALPHA   0.001f

// GEMM tiling
#define BM 64
#define BK 32
#define BN 64
#define NTHREADS 256

// Global accumulators for aux loss (zeroed via cudaMemsetAsync each launch)
__device__ float g_cnt[NEXP];    // selection counts (float; exactly representable)
__device__ float g_psum[NEXP];   // sum of softmax scores per expert

__global__ __launch_bounds__(NTHREADS)
void gate_kernel(const float* __restrict__ x,    // [T_TOK, HDIM]
                 const float* __restrict__ w,    // [NEXP, HDIM]
                 float* __restrict__ out_w,      // [T_TOK, TOPK]
                 float* __restrict__ out_i)      // [T_TOK, TOPK] (float-cast idx)
{
    __shared__ float As[BK][BM + 4];
    __shared__ float Bs[BK][BN + 4];
    __shared__ float sc[BM][BN + 1];   // logits, then scores
    __shared__ float cnt_s[NEXP];

    const int tid = threadIdx.x;
    const int m0  = blockIdx.x * BM;

    if (tid < NEXP) cnt_s[tid] = 0.0f;

    // compute-thread mapping: 16x16 thread grid, each 4x4 outputs
    const int tr = tid >> 4;          // 0..15
    const int tc = tid & 15;          // 0..15
    const int mreg = tr * 4;
    const int nreg = tc * 4;

    float acc[4][4];
#pragma unroll
    for (int i = 0; i < 4; i++)
#pragma unroll
        for (int j = 0; j < 4; j++) acc[i][j] = 0.0f;

    for (int k0 = 0; k0 < HDIM; k0 += BK) {
        // Load tiles: 64 rows x 32 k each for A (tokens) and B (experts).
        // 512 float4 per tile, 256 threads -> 2 float4 each.
#pragma unroll
        for (int i = 0; i < 2; i++) {
            int id  = tid + NTHREADS * i;
            int row = id >> 3;          // 0..63
            int kq  = id & 7;           // 0..7  (float4 along k)
            float4 av = *(const float4*)&x[(size_t)(m0 + row) * HDIM + k0 + kq * 4];
            As[kq * 4 + 0][row] = av.x;
            As[kq * 4 + 1][row] = av.y;
            As[kq * 4 + 2][row] = av.z;
            As[kq * 4 + 3][row] = av.w;
            float4 bv = *(const float4*)&w[(size_t)row * HDIM + k0 + kq * 4];
            Bs[kq * 4 + 0][row] = bv.x;
            Bs[kq * 4 + 1][row] = bv.y;
            Bs[kq * 4 + 2][row] = bv.z;
            Bs[kq * 4 + 3][row] = bv.w;
        }
        __syncthreads();

#pragma unroll
        for (int kk = 0; kk < BK; kk++) {
            float4 a4 = *(const float4*)&As[kk][mreg];
            float4 b4 = *(const float4*)&Bs[kk][nreg];
            float a[4] = {a4.x, a4.y, a4.z, a4.w};
            float b[4] = {b4.x, b4.y, b4.z, b4.w};
#pragma unroll
            for (int i = 0; i < 4; i++)
#pragma unroll
                for (int j = 0; j < 4; j++)
                    acc[i][j] = fmaf(a[i], b[j], acc[i][j]);
        }
        __syncthreads();
    }

    // Write logits to shared
#pragma unroll
    for (int i = 0; i < 4; i++)
#pragma unroll
        for (int j = 0; j < 4; j++)
            sc[mreg + i][nreg + j] = acc[i][j];
    __syncthreads();

    // Softmax + top-8 per token. 8 warps, each owns 8 tokens.
    const int wid  = tid >> 5;
    const int lane = tid & 31;

    for (int t = wid * 8; t < wid * 8 + 8; t++) {
        float v0 = sc[t][lane];
        float v1 = sc[t][lane + 32];
        float mx = fmaxf(v0, v1);
#pragma unroll
        for (int off = 16; off > 0; off >>= 1)
            mx = fmaxf(mx, __shfl_xor_sync(0xFFFFFFFFu, mx, off));
        float e0 = expf(v0 - mx);
        float e1 = expf(v1 - mx);
        float s = e0 + e1;
#pragma unroll
        for (int off = 16; off > 0; off >>= 1)
            s += __shfl_xor_sync(0xFFFFFFFFu, s, off);
        float inv = 1.0f / s;
        float s0 = e0 * inv;
        float s1 = e1 * inv;
        sc[t][lane]      = s0;   // store scores for column sums (Pi)
        sc[t][lane + 32] = s1;

        // iterative top-8 (descending, tie -> lower expert index)
        float r0 = s0, r1 = s1;
#pragma unroll
        for (int r = 0; r < TOPK; r++) {
            float bv; int bi;
            if (r0 >= r1) { bv = r0; bi = lane; }
            else          { bv = r1; bi = lane + 32; }
#pragma unroll
            for (int off = 16; off > 0; off >>= 1) {
                float ov = __shfl_xor_sync(0xFFFFFFFFu, bv, off);
                int   oi = __shfl_xor_sync(0xFFFFFFFFu, bi, off);
                if (ov > bv || (ov == bv && oi < bi)) { bv = ov; bi = oi; }
            }
            if (lane == 0) {
                out_w[(size_t)(m0 + t) * TOPK + r] = bv;
                out_i[(size_t)(m0 + t) * TOPK + r] = (float)bi;
                atomicAdd(&cnt_s[bi], 1.0f);
            }
            if (bi == lane)           r0 = -1.0f;
            else if (bi == lane + 32) r1 = -1.0f;
        }
    }
    __syncthreads();

    // Per-expert column sums of scores + flush to global accumulators
    if (tid < NEXP) {
        float s = 0.0f;
#pragma unroll 8
        for (int t = 0; t < BM; t++) s += sc[t][tid];
        atomicAdd(&g_psum[tid], s);
        atomicAdd(&g_cnt[tid],  cnt_s[tid]);
    }
}

__global__ void finalize_kernel(float* __restrict__ out)
{
    __shared__ float red[NEXP];
    int e = threadIdx.x;  // 64 threads
    float Pi = g_psum[e] / (float)T_TOK;
    float fi = g_cnt[e] / ((float)T_TOK * (float)TOPK) * (float)NEXP;
    red[e] = Pi * fi;
    __syncthreads();
    if (e < 32) {
        float v = red[e] + red[e + 32];
#pragma unroll
        for (int off = 16; off > 0; off >>= 1)
            v += __shfl_xor_sync(0xFFFFFFFFu, v, off);
        if (e == 0)
            out[(size_t)2 * T_TOK * TOPK] = v * ALPHA;
    }
}

extern "C" void kernel_launch(void* const* d_in, const int* in_sizes, int n_in,
                              void* d_out, int out_size)
{
    const float* hs = (const float*)d_in[0];   // [4,4096,4096] -> [16384,4096]
    const float* w  = (const float*)d_in[1];   // [64,4096]
    float* out  = (float*)d_out;
    float* outw = out;                          // [16384*8] topk weights
    float* outi = out + (size_t)T_TOK * TOPK;   // [16384*8] topk indices (float)

    void *cptr = nullptr, *pptr = nullptr;
    cudaGetSymbolAddress(&cptr, g_cnt);
    cudaGetSymbolAddress(&pptr, g_psum);
    cudaMemsetAsync(cptr, 0, NEXP * sizeof(float));
    cudaMemsetAsync(pptr, 0, NEXP * sizeof(float));

    gate_kernel<<<T_TOK / BM, NTHREADS>>>(hs, w, outw, outi);
    finalize_kernel<<<1, NEXP>>>(out);
}

// round 2
// speedup vs baseline: 1.1882x; 1.1882x over previous
#include <cuda_runtime.h>
#include <cuda_bf16.h>
#include <math.h>

// Problem constants
#define T_TOK   16384      // 4*4096 tokens
#define HDIM    4096
#define NEXP    64
#define TOPK    8
#define ALPHA   0.001f

// GEMM tiling
#define BM 64
#define BN 64
#define BK 32
#define BK2 (BK/2)         // k-pairs
#define BMP 66             // padded row length (float2 units) -> stride 132 words
#define NTHREADS 256

typedef unsigned long long ull;

// Global accumulators for aux loss (zeroed via cudaMemsetAsync each launch)
__device__ float g_cnt[NEXP];
__device__ float g_psum[NEXP];

__device__ __forceinline__ void ffma2(ull& acc, ull a, ull b) {
    asm("fma.rn.f32x2 %0, %1, %2, %0;" : "+l"(acc) : "l"(a), "l"(b));
}

__global__ __launch_bounds__(NTHREADS, 2)
void gate_kernel(const float* __restrict__ x,    // [T_TOK, HDIM]
                 const float* __restrict__ w,    // [NEXP, HDIM]
                 float* __restrict__ out_w,      // [T_TOK, TOPK]
                 float* __restrict__ out_i)      // [T_TOK, TOPK] (float idx)
{
    __shared__ float2 As2[BK2][BMP];   // [k-pair][token]  8.4KB
    __shared__ float2 Bs2[BK2][BMP];   // [k-pair][expert] 8.4KB
    __shared__ float  sc[BM][BN + 1];  // logits -> scores 16.6KB
    __shared__ float  cnt_s[NEXP];

    const int tid = threadIdx.x;
    const int m0  = blockIdx.x * BM;

    if (tid < NEXP) cnt_s[tid] = 0.0f;

    // compute mapping: 16x16 threads; thread owns tokens 4tr..4tr+3,
    // experts {tc, tc+16, tc+32, tc+48}
    const int tr = tid >> 4;
    const int tc = tid & 15;

    // load mapping: id = tid + 256*i ; row = id>>3 (0..63), kq = id&7 (float4 in k)
    const int l_row0 = tid >> 3;
    const int l_kq   = tid & 7;
    const int l_row1 = (tid + NTHREADS) >> 3;

    ull acc[4][4];
#pragma unroll
    for (int i = 0; i < 4; i++)
#pragma unroll
        for (int j = 0; j < 4; j++) acc[i][j] = 0ULL;

    // ---- preload tile 0 into regs
    float4 pA0 = *(const float4*)&x[(size_t)(m0 + l_row0) * HDIM + l_kq * 4];
    float4 pB0 = *(const float4*)&w[(size_t)l_row0 * HDIM + l_kq * 4];
    float4 pA1 = *(const float4*)&x[(size_t)(m0 + l_row1) * HDIM + l_kq * 4];
    float4 pB1 = *(const float4*)&w[(size_t)l_row1 * HDIM + l_kq * 4];

    for (int k0 = 0; k0 < HDIM; k0 += BK) {
        // store prefetched tile to smem
        As2[2 * l_kq][l_row0]     = make_float2(pA0.x, pA0.y);
        As2[2 * l_kq + 1][l_row0] = make_float2(pA0.z, pA0.w);
        Bs2[2 * l_kq][l_row0]     = make_float2(pB0.x, pB0.y);
        Bs2[2 * l_kq + 1][l_row0] = make_float2(pB0.z, pB0.w);
        As2[2 * l_kq][l_row1]     = make_float2(pA1.x, pA1.y);
        As2[2 * l_kq + 1][l_row1] = make_float2(pA1.z, pA1.w);
        Bs2[2 * l_kq][l_row1]     = make_float2(pB1.x, pB1.y);
        Bs2[2 * l_kq + 1][l_row1] = make_float2(pB1.z, pB1.w);
        __syncthreads();

        // issue next tile's global loads early (latency hidden by compute)
        int kn = k0 + BK;
        if (kn < HDIM) {
            pA0 = *(const float4*)&x[(size_t)(m0 + l_row0) * HDIM + kn + l_kq * 4];
            pB0 = *(const float4*)&w[(size_t)l_row0 * HDIM + kn + l_kq * 4];
            pA1 = *(const float4*)&x[(size_t)(m0 + l_row1) * HDIM + kn + l_kq * 4];
            pB1 = *(const float4*)&w[(size_t)l_row1 * HDIM + kn + l_kq * 4];
        }

#pragma unroll
        for (int kk = 0; kk < BK2; kk++) {
            ulonglong2 av0 = *(const ulonglong2*)&As2[kk][4 * tr];
            ulonglong2 av1 = *(const ulonglong2*)&As2[kk][4 * tr + 2];
            ull a2[4] = {av0.x, av0.y, av1.x, av1.y};
            ull b2[4];
#pragma unroll
            for (int j = 0; j < 4; j++)
                b2[j] = *(const ull*)&Bs2[kk][tc + 16 * j];
#pragma unroll
            for (int i = 0; i < 4; i++)
#pragma unroll
                for (int j = 0; j < 4; j++)
                    ffma2(acc[i][j], a2[i], b2[j]);
        }
        __syncthreads();
    }

    // write logits (lo+hi = even-k + odd-k partials) to shared
#pragma unroll
    for (int i = 0; i < 4; i++)
#pragma unroll
        for (int j = 0; j < 4; j++) {
            float2 v = *(float2*)&acc[i][j];
            sc[4 * tr + i][tc + 16 * j] = v.x + v.y;
        }
    __syncthreads();

    // Softmax + top-8 per token. 8 warps, each owns 8 tokens.
    const int wid  = tid >> 5;
    const int lane = tid & 31;

    for (int t = wid * 8; t < wid * 8 + 8; t++) {
        float v0 = sc[t][lane];
        float v1 = sc[t][lane + 32];
        float mx = fmaxf(v0, v1);
#pragma unroll
        for (int off = 16; off > 0; off >>= 1)
            mx = fmaxf(mx, __shfl_xor_sync(0xFFFFFFFFu, mx, off));
        float e0 = expf(v0 - mx);
        float e1 = expf(v1 - mx);
        float s = e0 + e1;
#pragma unroll
        for (int off = 16; off > 0; off >>= 1)
            s += __shfl_xor_sync(0xFFFFFFFFu, s, off);
        float inv = 1.0f / s;
        float s0 = e0 * inv;
        float s1 = e1 * inv;
        sc[t][lane]      = s0;
        sc[t][lane + 32] = s1;

        // iterative top-8 (descending, tie -> lower expert index)
        float r0 = s0, r1 = s1;
#pragma unroll
        for (int r = 0; r < TOPK; r++) {
            float bv; int bi;
            if (r0 >= r1) { bv = r0; bi = lane; }
            else          { bv = r1; bi = lane + 32; }
#pragma unroll
            for (int off = 16; off > 0; off >>= 1) {
                float ov = __shfl_xor_sync(0xFFFFFFFFu, bv, off);
                int   oi = __shfl_xor_sync(0xFFFFFFFFu, bi, off);
                if (ov > bv || (ov == bv && oi < bi)) { bv = ov; bi = oi; }
            }
            if (lane == 0) {
                out_w[(size_t)(m0 + t) * TOPK + r] = bv;
                out_i[(size_t)(m0 + t) * TOPK + r] = (float)bi;
                atomicAdd(&cnt_s[bi], 1.0f);
            }
            if (bi == lane)           r0 = -1.0f;
            else if (bi == lane + 32) r1 = -1.0f;
        }
    }
    __syncthreads();

    // Per-expert column sums of scores + flush to global accumulators
    if (tid < NEXP) {
        float s = 0.0f;
#pragma unroll 8
        for (int t = 0; t < BM; t++) s += sc[t][tid];
        atomicAdd(&g_psum[tid], s);
        atomicAdd(&g_cnt[tid],  cnt_s[tid]);
    }
}

__global__ void finalize_kernel(float* __restrict__ out)
{
    __shared__ float red[NEXP];
    int e = threadIdx.x;  // 64 threads
    float Pi = g_psum[e] / (float)T_TOK;
    float fi = g_cnt[e] / ((float)T_TOK * (float)TOPK) * (float)NEXP;
    red[e] = Pi * fi;
    __syncthreads();
    if (e < 32) {
        float v = red[e] + red[e + 32];
#pragma unroll
        for (int off = 16; off > 0; off >>= 1)
            v += __shfl_xor_sync(0xFFFFFFFFu, v, off);
        if (e == 0)
            out[(size_t)2 * T_TOK * TOPK] = v * ALPHA;
    }
}

extern "C" void kernel_launch(void* const* d_in, const int* in_sizes, int n_in,
                              void* d_out, int out_size)
{
    const float* hs = (const float*)d_in[0];   // [4,4096,4096] -> [16384,4096]
    const float* w  = (const float*)d_in[1];   // [64,4096]
    float* out  = (float*)d_out;
    float* outw = out;                          // topk weights [16384*8]
    float* outi = out + (size_t)T_TOK * TOPK;   // topk indices [16384*8]

    void *cptr = nullptr, *pptr = nullptr;
    cudaGetSymbolAddress(&cptr, g_cnt);
    cudaGetSymbolAddress(&pptr, g_psum);
    cudaMemsetAsync(cptr, 0, NEXP * sizeof(float));
    cudaMemsetAsync(pptr, 0, NEXP * sizeof(float));

    gate_kernel<<<T_TOK / BM, NTHREADS>>>(hs, w, outw, outi);
    finalize_kernel<<<1, NEXP>>>(out);
}